// round 1
// baseline (speedup 1.0000x reference)
#include <cuda_runtime.h>

#define B_ 4
#define S_ 2048
#define H_ 8
#define D_ 64
#define C_ 64
#define NC_ (S_/C_)      // 32 chunks per (b,h)
#define BH_ (B_*H_)      // 32
#define SCALE 0.125f     // 1/sqrt(64)

// Per-(bh,chunk) 64x64 KV state scratch: 32*32*4096 floats = 16 MB
__device__ float g_state[(size_t)BH_*NC_*D_*D_];

__device__ __forceinline__ float featf(float x) {
    // elu(x) + 1
    return x > 0.f ? x + 1.f : __expf(x);
}

#define FMA16(ACC, SCLR, PTR)                                              \
    do {                                                                    \
        const float4* _p = reinterpret_cast<const float4*>(PTR);           \
        float4 _a = _p[0], _b = _p[1], _c = _p[2], _d = _p[3];              \
        ACC[0]  += (SCLR) * _a.x; ACC[1]  += (SCLR) * _a.y;                 \
        ACC[2]  += (SCLR) * _a.z; ACC[3]  += (SCLR) * _a.w;                 \
        ACC[4]  += (SCLR) * _b.x; ACC[5]  += (SCLR) * _b.y;                 \
        ACC[6]  += (SCLR) * _b.z; ACC[7]  += (SCLR) * _b.w;                 \
        ACC[8]  += (SCLR) * _c.x; ACC[9]  += (SCLR) * _c.y;                 \
        ACC[10] += (SCLR) * _c.z; ACC[11] += (SCLR) * _c.w;                 \
        ACC[12] += (SCLR) * _d.x; ACC[13] += (SCLR) * _d.y;                 \
        ACC[14] += (SCLR) * _d.z; ACC[15] += (SCLR) * _d.w;                 \
    } while (0)

// ---------------------------------------------------------------------------
// Kernel 1: per-chunk KV sums.  state[d][e] = sum_j k[j][d]*v[j][e]
// grid: BH_*NC_ blocks, 256 threads. Thread owns (e = t&63, dq = t>>6): 16 d's.
// ---------------------------------------------------------------------------
__global__ void __launch_bounds__(256) k_chunk_sum(const float* __restrict__ qk,
                                                   const float* __restrict__ v) {
    __shared__ float k_sh[C_][D_ + 4];
    __shared__ float v_sh[C_][D_ + 4];

    const int t  = threadIdx.x;
    const int bh = blockIdx.x / NC_;
    const int c  = blockIdx.x % NC_;
    const int b  = bh / H_, h = bh % H_;
    const int s0 = c * C_;

    #pragma unroll
    for (int r = 0; r < 4; r++) {
        int idx = t + r * 256;          // float4 index within 64x64 tile
        int j   = idx >> 4;
        int d4  = (idx & 15) << 2;
        size_t s = (size_t)(s0 + j);
        const float4 kf = *reinterpret_cast<const float4*>(
            qk + ((((size_t)b * S_ + s) * 2 + 1) * H_ + h) * D_ + d4);
        float4 kk;
        kk.x = featf(kf.x) * SCALE; kk.y = featf(kf.y) * SCALE;
        kk.z = featf(kf.z) * SCALE; kk.w = featf(kf.w) * SCALE;
        *reinterpret_cast<float4*>(&k_sh[j][d4]) = kk;
        const float4 vf = *reinterpret_cast<const float4*>(
            v + (((size_t)b * S_ + s) * H_ + h) * D_ + d4);
        *reinterpret_cast<float4*>(&v_sh[j][d4]) = vf;
    }
    __syncthreads();

    const int e  = t & 63;
    const int dq = t >> 6;
    float acc[16];
    #pragma unroll
    for (int r = 0; r < 16; r++) acc[r] = 0.f;

    #pragma unroll 4
    for (int j = 0; j < C_; j++) {
        float vje = v_sh[j][e];
        FMA16(acc, vje, &k_sh[j][dq * 16]);
    }

    float* dst = g_state + (size_t)(bh * NC_ + c) * (D_ * D_);
    #pragma unroll
    for (int r = 0; r < 16; r++) dst[(dq * 16 + r) * D_ + e] = acc[r];
}

// ---------------------------------------------------------------------------
// Kernel 2: exclusive prefix sum of chunk states along chunk axis, per (b,h).
// grid: BH_ blocks, 256 threads; thread owns 16 strided elements of the 4096.
// ---------------------------------------------------------------------------
__global__ void __launch_bounds__(256) k_prefix() {
    const int bh = blockIdx.x;
    const int t  = threadIdx.x;
    float run[16];
    #pragma unroll
    for (int r = 0; r < 16; r++) run[r] = 0.f;

    float* base = g_state + (size_t)bh * NC_ * (D_ * D_);
    for (int c = 0; c < NC_; c++) {
        float* p = base + c * (D_ * D_);
        #pragma unroll
        for (int r = 0; r < 16; r++) {
            float tmp = p[r * 256 + t];
            p[r * 256 + t] = run[r];
            run[r] += tmp;
        }
    }
}

// ---------------------------------------------------------------------------
// Kernel 3: output.
//   out[i][e] = norm_i * ( sum_d q[i][d]*state[d][e]
//                        + sum_{j<=i} (q_i . k_j) * v[j][e] )
// grid: BH_*NC_ blocks, 256 threads. Thread owns (i = t&63, q16 = t>>6): 16 e's.
// ---------------------------------------------------------------------------
__global__ void __launch_bounds__(256) k_output(const float* __restrict__ qk,
                                                const float* __restrict__ v,
                                                const float* __restrict__ nvec,
                                                const float* __restrict__ offset,
                                                float* __restrict__ out) {
    extern __shared__ float sm[];
    float* qT = sm;                      // [64][65]  qT[d][i]
    float* kT = qT + 64 * 65;            // [64][68]  kT[d][j]
    float* vS = kT + 64 * 68;            // [64][68]  vS[j][e]
    float* A  = vS + 64 * 68;            // [64][67]  A[i][j]

    const int t  = threadIdx.x;
    const int bh = blockIdx.x / NC_;
    const int c  = blockIdx.x % NC_;
    const int b  = bh / H_, h = bh % H_;
    const int s0 = c * C_;

    #pragma unroll
    for (int r = 0; r < 4; r++) {
        int idx = t + r * 256;
        int row = idx >> 4;
        int d4  = (idx & 15) << 2;
        size_t s = (size_t)(s0 + row);
        const float4 qf = *reinterpret_cast<const float4*>(
            qk + ((((size_t)b * S_ + s) * 2 + 0) * H_ + h) * D_ + d4);
        qT[(d4 + 0) * 65 + row] = featf(qf.x);
        qT[(d4 + 1) * 65 + row] = featf(qf.y);
        qT[(d4 + 2) * 65 + row] = featf(qf.z);
        qT[(d4 + 3) * 65 + row] = featf(qf.w);
        const float4 kf = *reinterpret_cast<const float4*>(
            qk + ((((size_t)b * S_ + s) * 2 + 1) * H_ + h) * D_ + d4);
        kT[(d4 + 0) * 68 + row] = featf(kf.x) * SCALE;
        kT[(d4 + 1) * 68 + row] = featf(kf.y) * SCALE;
        kT[(d4 + 2) * 68 + row] = featf(kf.z) * SCALE;
        kT[(d4 + 3) * 68 + row] = featf(kf.w) * SCALE;
        const float4 vf = *reinterpret_cast<const float4*>(
            v + (((size_t)b * S_ + s) * H_ + h) * D_ + d4);
        *reinterpret_cast<float4*>(&vS[row * 68 + d4]) = vf;
    }
    __syncthreads();

    const int i    = t & 63;
    const int q16  = t >> 6;        // column group: both jq (phase A) and eq (out)
    const int imax = i | 31;        // uniform per warp

    // Phase 2a: A[i][j] = q_i . k_j for this thread's 16 j's (causal-masked).
    // Whole-warp skip when the j-block is entirely above the diagonal.
    if (q16 * 16 <= imax) {
        float a[16];
        #pragma unroll
        for (int r = 0; r < 16; r++) a[r] = 0.f;
        #pragma unroll 4
        for (int d = 0; d < 64; d++) {
            float qi = qT[d * 65 + i];
            FMA16(a, qi, &kT[d * 68 + q16 * 16]);
        }
        #pragma unroll
        for (int r = 0; r < 16; r++) {
            int j = q16 * 16 + r;
            A[i * 67 + j] = (j <= i) ? a[r] : 0.f;
        }
    }

    // Phase 1: o = q_i @ state (exclusive prefix state from global, L1-broadcast)
    float o[16];
    #pragma unroll
    for (int r = 0; r < 16; r++) o[r] = 0.f;
    const float* st = g_state + (size_t)(bh * NC_ + c) * (D_ * D_) + q16 * 16;
    #pragma unroll 4
    for (int d = 0; d < 64; d++) {
        float qi = qT[d * 65 + i];
        FMA16(o, qi, st + d * 64);
    }
    __syncthreads();

    // Phase 2b: o += A[i][:] @ v  (loop bound uniform per warp, causal skip)
    const int jmax = imax + 1;
    #pragma unroll 4
    for (int j = 0; j < jmax; j++) {
        float aij = A[i * 67 + j];
        FMA16(o, aij, &vS[j * 68 + q16 * 16]);
    }

    // Epilogue: norm = exp(-softplus(n+off)) = sigmoid(-(n+off))
    const size_t s = (size_t)(s0 + i);
    float z    = nvec[((size_t)b * S_ + s) * H_ + h] + offset[h];
    float norm = 1.f / (1.f + __expf(z));
    #pragma unroll
    for (int r = 0; r < 16; r++) o[r] *= norm;

    float* op = out + (((size_t)b * S_ + s) * H_ + h) * D_ + q16 * 16;
    float4 w;
    w.x = o[0];  w.y = o[1];  w.z = o[2];  w.w = o[3];
    reinterpret_cast<float4*>(op)[0] = w;
    w.x = o[4];  w.y = o[5];  w.z = o[6];  w.w = o[7];
    reinterpret_cast<float4*>(op)[1] = w;
    w.x = o[8];  w.y = o[9];  w.z = o[10]; w.w = o[11];
    reinterpret_cast<float4*>(op)[2] = w;
    w.x = o[12]; w.y = o[13]; w.z = o[14]; w.w = o[15];
    reinterpret_cast<float4*>(op)[3] = w;
}

// ---------------------------------------------------------------------------
extern "C" void kernel_launch(void* const* d_in, const int* in_sizes, int n_in,
                              void* d_out, int out_size) {
    (void)in_sizes; (void)n_in; (void)out_size;
    const float* qk     = (const float*)d_in[0];
    const float* v      = (const float*)d_in[1];
    const float* nvec   = (const float*)d_in[2];
    const float* offset = (const float*)d_in[3];
    float* out = (float*)d_out;

    const int smem3 = 64 * (65 + 68 + 68 + 67) * (int)sizeof(float);  // 68608 B
    cudaFuncSetAttribute(k_output, cudaFuncAttributeMaxDynamicSharedMemorySize, smem3);

    k_chunk_sum<<<BH_ * NC_, 256>>>(qk, v);
    k_prefix<<<BH_, 256>>>();
    k_output<<<BH_ * NC_, 256, smem3>>>(qk, v, nvec, offset, out);
}

// round 2
// speedup vs baseline: 1.6708x; 1.6708x over previous
#include <cuda_runtime.h>

#define B_ 4
#define S_ 2048
#define H_ 8
#define D_ 64
#define C_ 64
#define NC_ (S_/C_)      // 32 chunks per (b,h)
#define BH_ (B_*H_)      // 32
#define SCALE 0.125f     // 1/sqrt(64)

typedef unsigned long long ull;

// Per-(bh,chunk) 64x64 KV state scratch: 32*32*4096 floats = 16 MB
__device__ float g_state[(size_t)BH_*NC_*D_*D_];

__device__ __forceinline__ float featf(float x) {
    return x > 0.f ? x + 1.f : __expf(x);   // elu(x)+1
}

__device__ __forceinline__ void fma2(ull& d, ull a, ull b) {
    asm("fma.rn.f32x2 %0, %1, %2, %0;" : "+l"(d) : "l"(a), "l"(b));
}
__device__ __forceinline__ void mul2(ull& d, ull a, ull b) {
    asm("mul.rn.f32x2 %0, %1, %2;" : "=l"(d) : "l"(a), "l"(b));
}
__device__ __forceinline__ ull pack2(float x) {
    ull r; asm("mov.b64 %0, {%1, %1};" : "=l"(r) : "f"(x)); return r;
}
__device__ __forceinline__ float2 unpack2(ull p) {
    float2 f; asm("mov.b64 {%0, %1}, %2;" : "=f"(f.x), "=f"(f.y) : "l"(p)); return f;
}

// 16 MACs: 8 packed fma.f32x2 against 16 contiguous floats at PTR (16B aligned)
#define FMA16P(ACC, SP, PTR)                                                \
    do {                                                                     \
        const ulonglong2* _p = reinterpret_cast<const ulonglong2*>(PTR);     \
        ulonglong2 _a = _p[0], _b = _p[1], _c = _p[2], _d = _p[3];           \
        fma2(ACC[0], SP, _a.x); fma2(ACC[1], SP, _a.y);                      \
        fma2(ACC[2], SP, _b.x); fma2(ACC[3], SP, _b.y);                      \
        fma2(ACC[4], SP, _c.x); fma2(ACC[5], SP, _c.y);                      \
        fma2(ACC[6], SP, _d.x); fma2(ACC[7], SP, _d.y);                      \
    } while (0)

// ---------------------------------------------------------------------------
// Kernel 1: per-chunk KV sums.  state[d][e] = sum_j k[j][d]*v[j][e]
// grid: BH_*NC_ blocks, 256 threads. Thread owns (d = t&63, eq = t>>6): 16 e's.
// ---------------------------------------------------------------------------
__global__ void __launch_bounds__(256) k_chunk_sum(const float* __restrict__ qk,
                                                   const float* __restrict__ v) {
    __shared__ float k_sh[C_ * 68];
    __shared__ float v_sh[C_ * 68];

    const int t  = threadIdx.x;
    const int bh = blockIdx.x / NC_;
    const int c  = blockIdx.x % NC_;
    const int b  = bh / H_, h = bh % H_;
    const int s0 = c * C_;

    #pragma unroll
    for (int r = 0; r < 4; r++) {
        int idx = t + r * 256;          // float4 index within 64x64 tile
        int j   = idx >> 4;
        int d4  = (idx & 15) << 2;
        size_t s = (size_t)(s0 + j);
        const float4 kf = *reinterpret_cast<const float4*>(
            qk + ((((size_t)b * S_ + s) * 2 + 1) * H_ + h) * D_ + d4);
        float4 kk;
        kk.x = featf(kf.x) * SCALE; kk.y = featf(kf.y) * SCALE;
        kk.z = featf(kf.z) * SCALE; kk.w = featf(kf.w) * SCALE;
        *reinterpret_cast<float4*>(&k_sh[j * 68 + d4]) = kk;
        const float4 vf = *reinterpret_cast<const float4*>(
            v + (((size_t)b * S_ + s) * H_ + h) * D_ + d4);
        *reinterpret_cast<float4*>(&v_sh[j * 68 + d4]) = vf;
    }
    __syncthreads();

    const int d  = t & 63;
    const int eq = t >> 6;
    ull acc[8];
    #pragma unroll
    for (int r = 0; r < 8; r++) acc[r] = 0ull;

    #pragma unroll 8
    for (int j = 0; j < C_; j++) {
        ull kp = pack2(k_sh[j * 68 + d]);
        FMA16P(acc, kp, &v_sh[j * 68 + eq * 16]);
    }

    float* dst = g_state + (size_t)(bh * NC_ + c) * (D_ * D_) + d * D_ + eq * 16;
    ulonglong2* dp = reinterpret_cast<ulonglong2*>(dst);
    dp[0] = make_ulonglong2(acc[0], acc[1]);
    dp[1] = make_ulonglong2(acc[2], acc[3]);
    dp[2] = make_ulonglong2(acc[4], acc[5]);
    dp[3] = make_ulonglong2(acc[6], acc[7]);
}

// ---------------------------------------------------------------------------
// Kernel 2: exclusive prefix sum over chunks. One thread per state element.
// grid: 512 blocks x 256 threads = 131072 = BH_ * 4096 elements.
// ---------------------------------------------------------------------------
__global__ void __launch_bounds__(256) k_prefix() {
    const int el  = blockIdx.x * 256 + threadIdx.x;
    const int bh  = el >> 12;
    const int off = el & 4095;
    float* p = g_state + (size_t)bh * NC_ * (D_ * D_) + off;
    float run = 0.f;
    #pragma unroll
    for (int c = 0; c < NC_; c++) {
        float tmp = p[(size_t)c * (D_ * D_)];
        p[(size_t)c * (D_ * D_)] = run;
        run += tmp;
    }
}

// ---------------------------------------------------------------------------
// Kernel 3: output.
//   out[i][e] = norm_i * ( sum_d q[i][d]*state[d][e]
//                        + sum_{j<=i} (q_i . k_j) * v[j][e] )
// grid: BH_*NC_ blocks, 256 threads. Thread owns (i = t&63, q16 = t>>6).
// ---------------------------------------------------------------------------
__global__ void __launch_bounds__(256) k_output(const float* __restrict__ qk,
                                                const float* __restrict__ v,
                                                const float* __restrict__ nvec,
                                                const float* __restrict__ offset,
                                                float* __restrict__ out) {
    extern __shared__ float sm[];
    float* qT  = sm;                     // [64][65]  qT[d][i]
    float* kT  = qT + 64 * 65;           // [64][68]  kT[d][j]
    float* vS  = kT + 64 * 68;           // [64][68]  vS[j][e]
    float* A   = vS + 64 * 68;           // [64][65]  A[j][i]  (column-major!)
    float* stS = A  + 64 * 65;           // [64][68]  stS[d][e]

    const int t  = threadIdx.x;
    const int bh = blockIdx.x / NC_;
    const int c  = blockIdx.x % NC_;
    const int b  = bh / H_, h = bh % H_;
    const int s0 = c * C_;

    const float* stg = g_state + (size_t)(bh * NC_ + c) * (D_ * D_);

    #pragma unroll
    for (int r = 0; r < 4; r++) {
        int idx = t + r * 256;
        int row = idx >> 4;
        int d4  = (idx & 15) << 2;
        size_t s = (size_t)(s0 + row);
        const float4 qf = *reinterpret_cast<const float4*>(
            qk + ((((size_t)b * S_ + s) * 2 + 0) * H_ + h) * D_ + d4);
        qT[(d4 + 0) * 65 + row] = featf(qf.x);
        qT[(d4 + 1) * 65 + row] = featf(qf.y);
        qT[(d4 + 2) * 65 + row] = featf(qf.z);
        qT[(d4 + 3) * 65 + row] = featf(qf.w);
        const float4 kf = *reinterpret_cast<const float4*>(
            qk + ((((size_t)b * S_ + s) * 2 + 1) * H_ + h) * D_ + d4);
        kT[(d4 + 0) * 68 + row] = featf(kf.x) * SCALE;
        kT[(d4 + 1) * 68 + row] = featf(kf.y) * SCALE;
        kT[(d4 + 2) * 68 + row] = featf(kf.z) * SCALE;
        kT[(d4 + 3) * 68 + row] = featf(kf.w) * SCALE;
        const float4 vf = *reinterpret_cast<const float4*>(
            v + (((size_t)b * S_ + s) * H_ + h) * D_ + d4);
        *reinterpret_cast<float4*>(&vS[row * 68 + d4]) = vf;
        // stage exclusive-prefix state tile into smem
        const float4 sf = *reinterpret_cast<const float4*>(stg + row * D_ + d4);
        *reinterpret_cast<float4*>(&stS[row * 68 + d4]) = sf;
    }
    __syncthreads();

    const int i    = t & 63;
    const int q16  = t >> 6;
    const int imax = i | 31;                     // warp-uniform
    const bool activeA = (q16 * 16 <= imax);     // warp-uniform causal skip

    // Fused: o = q_i @ state   and   a = q_i . k_j (j in this q16 group)
    ull o[8], a[8];
    #pragma unroll
    for (int r = 0; r < 8; r++) { o[r] = 0ull; a[r] = 0ull; }

    #pragma unroll 8
    for (int d = 0; d < 64; d++) {
        ull qp = pack2(qT[d * 65 + i]);
        FMA16P(o, qp, &stS[d * 68 + q16 * 16]);
        if (activeA) FMA16P(a, qp, &kT[d * 68 + q16 * 16]);
    }

    // Masked store of A (column-major: conflict-free scalar stores/loads)
    if (activeA) {
        #pragma unroll
        for (int r = 0; r < 8; r++) {
            float2 f = unpack2(a[r]);
            int j0 = q16 * 16 + 2 * r;
            A[(j0 + 0) * 65 + i] = (j0     <= i) ? f.x : 0.f;
            A[(j0 + 1) * 65 + i] = (j0 + 1 <= i) ? f.y : 0.f;
        }
    }
    __syncthreads();

    // o += A[:,i] @ v   (loop bound warp-uniform; lower half does 32 iters)
    const int jmax = imax + 1;
    #pragma unroll 8
    for (int j = 0; j < jmax; j++) {
        ull ap = pack2(A[j * 65 + i]);
        FMA16P(o, ap, &vS[j * 68 + q16 * 16]);
    }

    // Epilogue: norm = exp(-softplus(n+off)) = sigmoid(-(n+off))
    const size_t s = (size_t)(s0 + i);
    float z    = nvec[((size_t)b * S_ + s) * H_ + h] + offset[h];
    float norm = 1.f / (1.f + __expf(z));
    ull np = pack2(norm);
    #pragma unroll
    for (int r = 0; r < 8; r++) mul2(o[r], o[r], np);

    float* op = out + (((size_t)b * S_ + s) * H_ + h) * D_ + q16 * 16;
    ulonglong2* ov = reinterpret_cast<ulonglong2*>(op);
    ov[0] = make_ulonglong2(o[0], o[1]);
    ov[1] = make_ulonglong2(o[2], o[3]);
    ov[2] = make_ulonglong2(o[4], o[5]);
    ov[3] = make_ulonglong2(o[6], o[7]);
}

// ---------------------------------------------------------------------------
extern "C" void kernel_launch(void* const* d_in, const int* in_sizes, int n_in,
                              void* d_out, int out_size) {
    (void)in_sizes; (void)n_in; (void)out_size;
    const float* qk     = (const float*)d_in[0];
    const float* v      = (const float*)d_in[1];
    const float* nvec   = (const float*)d_in[2];
    const float* offset = (const float*)d_in[3];
    float* out = (float*)d_out;

    const int smem3 = (64 * (65 + 68 + 68 + 65 + 68)) * (int)sizeof(float); // 85504 B
    cudaFuncSetAttribute(k_output, cudaFuncAttributeMaxDynamicSharedMemorySize, smem3);

    k_chunk_sum<<<BH_ * NC_, 256>>>(qk, v);
    k_prefix<<<512, 256>>>();
    k_output<<<BH_ * NC_, 256, smem3>>>(qk, v, nvec, offset, out);
}